// round 16
// baseline (speedup 1.0000x reference)
#include <cuda_runtime.h>
#include <cuda_bf16.h>
#include <cuda_fp16.h>
#include <math.h>
#include <stdint.h>

#define BB 2
#define TT 2048
#define DD 1024
#define NH 16
#define NKV 4
#define HD 64
#define NREP 4           // NH / NKV
#define MM (BB*TT)       // 4096
#define NQKV (NH*HD + 2*NKV*HD)   // 1536 fused QKV output width

// ---------------- scratch (device globals; no runtime allocation) -----------
__device__ __align__(16) float g_cos[TT*32];
__device__ __align__(16) float g_sin[TT*32];
__device__ __half g_x16[MM*DD];                     // x fp16
__device__ __half g_w16[NQKV*DD];                   // fused QKV weights^T fp16 [N][K]
__device__ __half g_wo16[DD*DD];                    // Wo^T fp16 [N][K]
__device__ __half g_q16[BB*NH*TT*HD];               // Q fp16 [b][h][t][d]
__device__ __half g_k16[BB*NKV*TT*HD];              // K fp16 [b][kvh][t][d]
__device__ __half g_v16[BB*NKV*TT*HD];              // V fp16 [b][kvh][t][d]
__device__ __half g_a16[MM*DD];                     // attention out fp16

// ---------------- helpers ----------------------------------------------------
__device__ __forceinline__ uint32_t smem_u32(const void* p) {
    uint32_t a;
    asm("{ .reg .u64 t; cvta.to.shared.u64 t, %1; cvt.u32.u64 %0, t; }"
        : "=r"(a) : "l"(p));
    return a;
}
#define SWZ(off) ((off) ^ (((off) >> 3) & 0x70))

#define CP_ASYNC16(dst, src) \
    asm volatile("cp.async.cg.shared.global [%0], [%1], 16;" \
                 :: "r"(dst), "l"(src) : "memory")
#define CP_COMMIT() asm volatile("cp.async.commit_group;" ::: "memory")
#define CP_WAIT(n)  asm volatile("cp.async.wait_group %0;" :: "n"(n) : "memory")

#define LDSM4(r0, r1, r2, r3, addr) \
    asm volatile("ldmatrix.sync.aligned.m8n8.x4.shared.b16 {%0,%1,%2,%3}, [%4];" \
                 : "=r"(r0), "=r"(r1), "=r"(r2), "=r"(r3) : "r"(addr))

#define LDSM4T(r0, r1, r2, r3, addr) \
    asm volatile("ldmatrix.sync.aligned.m8n8.x4.trans.shared.b16 {%0,%1,%2,%3}, [%4];" \
                 : "=r"(r0), "=r"(r1), "=r"(r2), "=r"(r3) : "r"(addr))

#define MMAH(c, a, b0, b1) \
    asm volatile("mma.sync.aligned.m16n8k16.row.col.f32.f16.f16.f32 " \
                 "{%0,%1,%2,%3}, {%4,%5,%6,%7}, {%8,%9}, {%0,%1,%2,%3};" \
                 : "+f"((c)[0]), "+f"((c)[1]), "+f"((c)[2]), "+f"((c)[3]) \
                 : "r"((a)[0]), "r"((a)[1]), "r"((a)[2]), "r"((a)[3]), \
                   "r"(b0), "r"(b1))

#define EX2F16X2(d, a) \
    asm volatile("ex2.approx.f16x2 %0, %1;" : "=r"(d) : "r"(a))

__device__ __forceinline__ uint32_t packh(float a, float b) {
    __half2 h = __floats2half2_rn(a, b);
    return *(uint32_t*)&h;
}

// ---------------------------------------------------------------------------
// QKV GEMM: x(fp16) @ W(fp16)^T, fp32 acc. 64x128 CTA tile, 128 threads,
// BK=64, 3-stage cp.async (3 x 24KB) -> 2 CTAs/SM.
// Fused epilogue: RoPE (smem-staged cos/sin), Q/K/V -> fp16.
// ---------------------------------------------------------------------------
__global__ __launch_bounds__(128, 2) void gemm_qkv(
        const __half* __restrict__ A, const __half* __restrict__ B16,
        int M, int N, int K) {
    extern __shared__ char smem[];
    uint32_t sbase = smem_u32(smem);
    int tid = threadIdx.x, wid = tid >> 5, lid = tid & 31;
    int m0 = blockIdx.y * 64, n0 = blockIdx.x * 128;
    const int nch = K / 64;
    const int rr = tid >> 3, uu = tid & 7;   // rr 0..15

    float acc[4][4][4] = {};

    auto load_chunk = [&](int buf, int ch) {
        int k0 = ch * 64;
        uint32_t dbase = sbase + (uint32_t)buf * 24576u;
        #pragma unroll
        for (int it = 0; it < 4; it++) {       // A: 64 rows
            int r = it * 16 + rr;
            CP_ASYNC16(dbase + SWZ(r * 128 + uu * 16),
                       A + (size_t)(m0 + r) * K + k0 + uu * 8);
        }
        #pragma unroll
        for (int it = 0; it < 8; it++) {       // B: 128 rows
            int r = it * 16 + rr;
            CP_ASYNC16(dbase + 8192u + SWZ(r * 128 + uu * 16),
                       B16 + (size_t)(n0 + r) * K + k0 + uu * 8);
        }
        CP_COMMIT();
    };

    load_chunk(0, 0);
    load_chunk(1, 1);

    for (int ch = 0; ch < nch; ch++) {
        if (ch < nch - 1) { CP_WAIT(1); } else { CP_WAIT(0); }
        __syncthreads();
        if (ch + 2 < nch) load_chunk((ch + 2) % 3, ch + 2);

        uint32_t db = sbase + (uint32_t)(ch % 3) * 24576u;
        uint32_t ab_ = db, bb = db + 8192u;
        int g = lid >> 3, w8 = lid & 7;

        #pragma unroll
        for (int ks = 0; ks < 4; ks++) {
            uint32_t ah[4][4], bh[4][2];
            int arow = lid & 15;
            int acol = ks * 32 + (lid >> 4) * 16;
            #pragma unroll
            for (int mi = 0; mi < 4; mi++) {
                uint32_t off = SWZ((arow + mi * 16) * 128 + acol);
                LDSM4(ah[mi][0], ah[mi][1], ah[mi][2], ah[mi][3], ab_ + off);
            }
            #pragma unroll
            for (int p = 0; p < 2; p++) {
                int nrow = wid * 32 + p * 16 + (g >> 1) * 8 + w8;
                uint32_t off = SWZ(nrow * 128 + ks * 32 + (g & 1) * 16);
                LDSM4(bh[2*p][0], bh[2*p][1], bh[2*p+1][0], bh[2*p+1][1], bb + off);
            }
            #pragma unroll
            for (int mi = 0; mi < 4; mi++)
                #pragma unroll
                for (int ni = 0; ni < 4; ni++)
                    MMAH(acc[mi][ni], ah[mi], bh[ni][0], bh[ni][1]);
        }
        __syncthreads();
    }

    // ---- fused epilogue ----
    int region = (blockIdx.x < 8) ? 0 : (blockIdx.x < 10) ? 1 : 2;
    float* cs_s = (float*)smem;               // 8KB: cos[64][32]
    float* sn_s = (float*)(smem + 8192);      // 8KB: sin[64][32]
    if (region < 2) {
        int tbase = m0 & (TT - 1);
        #pragma unroll
        for (int i = 0; i < 4; i++) {
            int idx = i * 128 + tid;
            *(float4*)(smem + idx * 16) =
                *(const float4*)&g_cos[(size_t)tbase * 32 + idx * 4];
            *(float4*)(smem + 8192 + idx * 16) =
                *(const float4*)&g_sin[(size_t)tbase * 32 + idx * 4];
        }
        __syncthreads();
    }
    #pragma unroll
    for (int mi = 0; mi < 4; mi++) {
        int row = m0 + mi * 16 + (lid >> 2);
        #pragma unroll
        for (int r2 = 0; r2 < 2; r2++) {
            int trow = row + r2 * 8;
            int b = trow >> 11, t = trow & (TT - 1);
            int tl = trow - m0;
            #pragma unroll
            for (int ni = 0; ni < 4; ni++) {
                int c = n0 + wid * 32 + ni * 8 + (lid & 3) * 2;
                float v0 = acc[mi][ni][r2 * 2], v1 = acc[mi][ni][r2 * 2 + 1];
                if (region == 2) {
                    int cc = c - 1280;
                    int kvh = cc >> 6, d = cc & 63;
                    *(uint32_t*)&g_v16[((size_t)(b * NKV + kvh) * TT + t) * HD + d] =
                        packh(v0, v1);
                } else {
                    int cc = (region == 1) ? c - 1024 : c;
                    int hh = cc >> 6, d = cc & 63;
                    int ci = tl * 32 + (d >> 1);
                    float cs = cs_s[ci], sn = sn_s[ci];
                    float r0 = v0 * cs - v1 * sn;
                    float r1 = v1 * cs + v0 * sn;
                    if (region == 1) {
                        size_t o = ((size_t)(b * NKV + hh) * TT + t) * HD + d;
                        *(uint32_t*)&g_k16[o] = packh(r0, r1);
                    } else {
                        size_t o = ((size_t)(b * NH + hh) * TT + t) * HD + d;
                        *(uint32_t*)&g_q16[o] = packh(r0, r1);
                    }
                }
            }
        }
    }
}

// ---------------------------------------------------------------------------
// O-projection GEMM: single-term fp16 x fp16 (fp32 acc).
// 64x128 CTA tile, 128 threads, 3-stage (3 x 24KB) -> 2 CTAs/SM.
// ---------------------------------------------------------------------------
__global__ __launch_bounds__(128, 2) void gemm_out(
        const __half* __restrict__ A, const __half* __restrict__ B,
        float* __restrict__ C, int M, int N, int K) {
    extern __shared__ char smem[];
    uint32_t sbase = smem_u32(smem);
    int tid = threadIdx.x, wid = tid >> 5, lid = tid & 31;
    int m0 = blockIdx.y * 64, n0 = blockIdx.x * 128;
    const int nch = K / 64;
    const int rr = tid >> 3, uu = tid & 7;

    float acc[4][4][4] = {};

    auto load_chunk = [&](int buf, int ch) {
        int k0 = ch * 64;
        uint32_t dbase = sbase + (uint32_t)buf * 24576u;
        #pragma unroll
        for (int it = 0; it < 4; it++) {
            int r = it * 16 + rr;
            CP_ASYNC16(dbase + SWZ(r * 128 + uu * 16),
                       A + (size_t)(m0 + r) * K + k0 + uu * 8);
        }
        #pragma unroll
        for (int it = 0; it < 8; it++) {
            int r = it * 16 + rr;
            CP_ASYNC16(dbase + 8192u + SWZ(r * 128 + uu * 16),
                       B + (size_t)(n0 + r) * K + k0 + uu * 8);
        }
        CP_COMMIT();
    };

    load_chunk(0, 0);
    load_chunk(1, 1);

    for (int ch = 0; ch < nch; ch++) {
        if (ch < nch - 1) { CP_WAIT(1); } else { CP_WAIT(0); }
        __syncthreads();
        if (ch + 2 < nch) load_chunk((ch + 2) % 3, ch + 2);

        uint32_t db = sbase + (uint32_t)(ch % 3) * 24576u;
        uint32_t ab_ = db, bb = db + 8192u;
        int g = lid >> 3, w8 = lid & 7;

        #pragma unroll
        for (int ks = 0; ks < 4; ks++) {
            uint32_t ah[4][4], bh[4][2];
            int arow = lid & 15;
            int acol = ks * 32 + (lid >> 4) * 16;
            #pragma unroll
            for (int mi = 0; mi < 4; mi++) {
                uint32_t off = SWZ((arow + mi * 16) * 128 + acol);
                LDSM4(ah[mi][0], ah[mi][1], ah[mi][2], ah[mi][3], ab_ + off);
            }
            #pragma unroll
            for (int p = 0; p < 2; p++) {
                int nrow = wid * 32 + p * 16 + (g >> 1) * 8 + w8;
                uint32_t off = SWZ(nrow * 128 + ks * 32 + (g & 1) * 16);
                LDSM4(bh[2*p][0], bh[2*p][1], bh[2*p+1][0], bh[2*p+1][1], bb + off);
            }
            #pragma unroll
            for (int mi = 0; mi < 4; mi++)
                #pragma unroll
                for (int ni = 0; ni < 4; ni++)
                    MMAH(acc[mi][ni], ah[mi], bh[ni][0], bh[ni][1]);
        }
        __syncthreads();
    }

    #pragma unroll
    for (int mi = 0; mi < 4; mi++) {
        int row = m0 + mi * 16 + (lid >> 2);
        #pragma unroll
        for (int ni = 0; ni < 4; ni++) {
            int col = n0 + wid * 32 + ni * 8 + (lid & 3) * 2;
            *(float2*)&C[(size_t)row * N + col] =
                make_float2(acc[mi][ni][0], acc[mi][ni][1]);
            *(float2*)&C[(size_t)(row + 8) * N + col] =
                make_float2(acc[mi][ni][2], acc[mi][ni][3]);
        }
    }
}

// ---------------------------------------------------------------------------
// HMMA flash attention, causal. 64-query tiles, 128-KEY chunks, 128 threads,
// grid (T/64 reversed, B*NH). smem: Q 8KB + 2 x 32KB = 72KB -> 3 CTAs/SM.
// S fp16; softmax via ex2.approx.f16x2 (once per 128 keys); l via ones-MMA;
// PV fp16 (V via ldmatrix.trans). Mask on last chunk only.
// ---------------------------------------------------------------------------
__global__ __launch_bounds__(128, 3) void attn_mma(
        const __half* __restrict__ Q16, const __half* __restrict__ K16,
        const __half* __restrict__ Vt, __half* __restrict__ Oh) {
    extern __shared__ char smem[];
    uint32_t sbase = smem_u32(smem);
    const uint32_t QHI = 0, BUF = 8192;   // 2 x 32KB chunk buffers (K 16K | V 16K)

    int tid = threadIdx.x, wid = tid >> 5, lid = tid & 31;
    int qt = gridDim.x - 1 - blockIdx.x;
    int bh = blockIdx.y;
    int b = bh / NH, h = bh % NH, kvh = h / NREP;
    int q0 = qt * 64;

    const __half* qb16 = Q16 + (size_t)(b * NH + h) * TT * HD;
    const __half* kb16 = K16 + (size_t)(b * NKV + kvh) * TT * HD;
    const __half* vbase = Vt + (size_t)(b * NKV + kvh) * TT * HD;   // [t][d]

    // stage Q (own commit group): 64 rows
    {
        #pragma unroll
        for (int it = 0; it < 4; it++) {
            int idx = it * 128 + tid;
            int r = idx >> 3, u = idx & 7;
            CP_ASYNC16(sbase + QHI + SWZ(r * 128 + u * 16),
                       qb16 + (size_t)(q0 + r) * HD + u * 8);
        }
        CP_COMMIT();
    }

    // load one 128-key chunk (K + V)
    auto load_chunk = [&](int buf, int kt2) {
        uint32_t db = sbase + BUF + (uint32_t)buf * 32768u;
        #pragma unroll
        for (int arr = 0; arr < 2; arr++) {
            uint32_t ab = db + (uint32_t)arr * 16384u;
            const __half* s = arr ? vbase : kb16;
            #pragma unroll
            for (int it = 0; it < 8; it++) {
                int idx = it * 128 + tid;
                int r = idx >> 3, u = idx & 7;
                CP_ASYNC16(ab + SWZ(r * 128 + u * 16),
                           s + (size_t)(kt2 * 128 + r) * HD + u * 8);
            }
        }
        CP_COMMIT();
    };

    int nch = (qt + 2) >> 1;               // # of 128-key chunks
    load_chunk(0, 0);
    if (nch > 1) load_chunk(1, 1); else CP_COMMIT();

    CP_WAIT(2);
    __syncthreads();
    uint32_t qf[4][4];
    {
        int arow = wid * 16 + (lid & 15);
        #pragma unroll
        for (int ks = 0; ks < 4; ks++) {
            uint32_t off = SWZ(arow * 128 + ks * 32 + (lid >> 4) * 16);
            LDSM4(qf[ks][0], qf[ks][1], qf[ks][2], qf[ks][3], sbase + QHI + off);
        }
    }

    float oacc[8][4] = {};
    float lacc[4] = {};
    float mA = -1e30f, mB = -1e30f;
    const int g = lid >> 3, w8 = lid & 7;
    const int qrA = q0 + wid * 16 + (lid >> 2);
    const float SC = 0.125f * 1.4426950408889634f;   // scale * log2(e)
    const int vrow16 = lid & 15, vhi16 = (lid >> 4) & 1;
    const uint32_t ONES = 0x3C003C00u;

    for (int ch = 0; ch < nch; ch++) {
        if (ch < nch - 1) { CP_WAIT(1); } else { CP_WAIT(0); }
        __syncthreads();

        uint32_t kb = sbase + BUF + (uint32_t)(ch & 1) * 32768u;
        uint32_t vb = kb + 16384u;

        // ---- S = Q K^T over 128 keys ----
        float sacc[16][4] = {};
        #pragma unroll
        for (int ks = 0; ks < 4; ks++) {
            #pragma unroll
            for (int p = 0; p < 8; p++) {
                int nrow = p * 16 + (g >> 1) * 8 + w8;
                uint32_t off = SWZ(nrow * 128 + ks * 32 + (g & 1) * 16);
                uint32_t b0, b1, b2, b3;
                LDSM4(b0, b1, b2, b3, kb + off);
                MMAH(sacc[2*p],   qf[ks], b0, b1);
                MMAH(sacc[2*p+1], qf[ks], b2, b3);
            }
        }

        // ---- scale; mask (last chunk only) ----
        #pragma unroll
        for (int nt = 0; nt < 16; nt++)
            #pragma unroll
            for (int j = 0; j < 4; j++) sacc[nt][j] *= SC;
        if (ch == nch - 1) {
            #pragma unroll
            for (int nt = 0; nt < 16; nt++) {
                int kc = ch * 128 + nt * 8 + (lid & 3) * 2;
                if (kc > qrA)         sacc[nt][0] = -1e9f;
                if (kc + 1 > qrA)     sacc[nt][1] = -1e9f;
                if (kc > qrA + 8)     sacc[nt][2] = -1e9f;
                if (kc + 1 > qrA + 8) sacc[nt][3] = -1e9f;
            }
        }

        // ---- running max + rescale (corr-skip) ----
        float rmA = -1e30f, rmB = -1e30f;
        #pragma unroll
        for (int nt = 0; nt < 16; nt++) {
            rmA = fmaxf(rmA, fmaxf(sacc[nt][0], sacc[nt][1]));
            rmB = fmaxf(rmB, fmaxf(sacc[nt][2], sacc[nt][3]));
        }
        rmA = fmaxf(rmA, __shfl_xor_sync(0xffffffffu, rmA, 1));
        rmA = fmaxf(rmA, __shfl_xor_sync(0xffffffffu, rmA, 2));
        rmB = fmaxf(rmB, __shfl_xor_sync(0xffffffffu, rmB, 1));
        rmB = fmaxf(rmB, __shfl_xor_sync(0xffffffffu, rmB, 2));
        float mnA = fmaxf(mA, rmA), mnB = fmaxf(mB, rmB);
        if (mnA > mA || mnB > mB) {
            float corrA = exp2f(mA - mnA), corrB = exp2f(mB - mnB);
            #pragma unroll
            for (int nt = 0; nt < 8; nt++) {
                oacc[nt][0] *= corrA; oacc[nt][1] *= corrA;
                oacc[nt][2] *= corrB; oacc[nt][3] *= corrB;
            }
            lacc[0] *= corrA; lacc[1] *= corrA;
            lacc[2] *= corrB; lacc[3] *= corrB;
        }
        mA = mnA; mB = mnB;

        // ---- per 16-key group: P = ex2(s-m) fp16; l-MMA; PV ----
        #pragma unroll
        for (int k2 = 0; k2 < 8; k2++) {
            uint32_t pa[4];
            uint32_t t0 = packh(sacc[2*k2][0] - mA,   sacc[2*k2][1] - mA);
            uint32_t t1 = packh(sacc[2*k2][2] - mB,   sacc[2*k2][3] - mB);
            uint32_t t2 = packh(sacc[2*k2+1][0] - mA, sacc[2*k2+1][1] - mA);
            uint32_t t3 = packh(sacc[2*k2+1][2] - mB, sacc[2*k2+1][3] - mB);
            EX2F16X2(pa[0], t0);
            EX2F16X2(pa[1], t1);
            EX2F16X2(pa[2], t2);
            EX2F16X2(pa[3], t3);

            MMAH(lacc, pa, ONES, ONES);

            #pragma unroll
            for (int p = 0; p < 4; p++) {
                uint32_t off = SWZ((k2 * 16 + vrow16) * 128 + p * 32 + vhi16 * 16);
                uint32_t b0, b1, b2, b3;
                LDSM4T(b0, b1, b2, b3, vb + off);
                MMAH(oacc[2*p],   pa, b0, b1);
                MMAH(oacc[2*p+1], pa, b2, b3);
            }
        }
        __syncthreads();
        if (ch + 2 < nch) load_chunk(ch & 1, ch + 2);
    }

    // ---- epilogue: normalize, fp16 store ----
    float invA = 1.f / lacc[0], invB = 1.f / lacc[2];
    size_t rowA = (size_t)(b * TT + qrA);
    size_t rowB = rowA + 8;
    int colb = h * HD + (lid & 3) * 2;
    #pragma unroll
    for (int nt = 0; nt < 8; nt++) {
        *(uint32_t*)&Oh[rowA * DD + colb + nt * 8] =
            packh(oacc[nt][0] * invA, oacc[nt][1] * invA);
        *(uint32_t*)&Oh[rowB * DD + colb + nt * 8] =
            packh(oacc[nt][2] * invB, oacc[nt][3] * invB);
    }
}

// ---------------------------------------------------------------------------
// prep: x fp16 convert + fused QKV weight transpose (fp16) +
// Wo transpose (fp16) + rope table (sections on blockIdx.x)
// ---------------------------------------------------------------------------
__device__ __forceinline__ void convT16_body(const float* __restrict__ W,
        __half* __restrict__ t16, int Kd, int Nd, int idx, int tid, float (*Ts)[33]) {
    int nt = idx % (Nd / 32), kt = idx / (Nd / 32);
    int k0 = kt * 32, n0 = nt * 32;
    int r = tid >> 3, c4 = (tid & 7) * 4;
    float4 v = *(const float4*)&W[(size_t)(k0 + r) * Nd + n0 + c4];
    Ts[r][c4] = v.x; Ts[r][c4 + 1] = v.y; Ts[r][c4 + 2] = v.z; Ts[r][c4 + 3] = v.w;
    __syncthreads();
    #pragma unroll
    for (int j = 0; j < 4; j++) {
        size_t o = (size_t)(n0 + r) * Kd + k0 + c4 + j;
        t16[o] = __float2half_rn(Ts[c4 + j][r]);
    }
}

__global__ __launch_bounds__(256) void prep(const float* __restrict__ x,
        const float* __restrict__ Wq, const float* __restrict__ Wk,
        const float* __restrict__ Wv, const float* __restrict__ Wo) {
    __shared__ float Ts[32][33];
    int bx = blockIdx.x, tid = threadIdx.x;
    if (bx < 4096) {                       // x fp16 convert
        int i = (bx * 256 + tid) * 4;
        float4 v = *(const float4*)(x + i);
        *(uint32_t*)&g_x16[i]     = packh(v.x, v.y);
        *(uint32_t*)&g_x16[i + 2] = packh(v.z, v.w);
    } else if (bx < 5120) {
        convT16_body(Wq, g_w16, DD, DD, bx - 4096, tid, Ts);
    } else if (bx < 5376) {
        convT16_body(Wk, g_w16 + (size_t)NH * HD * DD, DD, NKV * HD, bx - 5120, tid, Ts);
    } else if (bx < 5632) {
        convT16_body(Wv, g_w16 + (size_t)(NH + NKV) * HD * DD, DD, NKV * HD,
                     bx - 5376, tid, Ts);
    } else if (bx < 6656) {
        convT16_body(Wo, g_wo16, DD, DD, bx - 5632, tid, Ts);
    } else {                               // rope table (fp32 trig; freq kept
                                           // bit-identical via double pow)
        int idx = (bx - 6656) * 256 + tid;
        int t = idx >> 5, pair = idx & 31;
        float freq = (float)pow(500000.0, -(double)pair / 32.0);
        float ang = (float)t * freq;
        float s, c;
        sincosf(ang, &s, &c);
        g_cos[idx] = c;
        g_sin[idx] = s;
    }
}

// ---------------------------------------------------------------------------
extern "C" void kernel_launch(void* const* d_in, const int* in_sizes, int n_in,
                              void* d_out, int out_size) {
    const float* x  = (const float*)d_in[0];
    // d_in[1] = causal mask — handled analytically
    const float* Wq = (const float*)d_in[2];
    const float* Wk = (const float*)d_in[3];
    const float* Wv = (const float*)d_in[4];
    const float* Wo = (const float*)d_in[5];
    float* out = (float*)d_out;

    __half *x16, *w16, *wo16;
    __half *q16, *k16, *v16, *a16;
    cudaGetSymbolAddress((void**)&x16, g_x16);
    cudaGetSymbolAddress((void**)&w16,  g_w16);
    cudaGetSymbolAddress((void**)&wo16, g_wo16);
    cudaGetSymbolAddress((void**)&q16, g_q16);
    cudaGetSymbolAddress((void**)&k16, g_k16);
    cudaGetSymbolAddress((void**)&v16, g_v16);
    cudaGetSymbolAddress((void**)&a16, g_a16);

    cudaFuncSetAttribute(gemm_qkv, cudaFuncAttributeMaxDynamicSharedMemorySize, 73728);
    cudaFuncSetAttribute(gemm_out, cudaFuncAttributeMaxDynamicSharedMemorySize, 73728);
    cudaFuncSetAttribute(attn_mma, cudaFuncAttributeMaxDynamicSharedMemorySize, 73728);

    prep<<<6912, 256>>>(x, Wq, Wk, Wv, Wo);

    // fused QKV projection + RoPE epilogue
    gemm_qkv<<<dim3(NQKV / 128, MM / 64), 128, 73728>>>(x16, w16, MM, NQKV, DD);

    attn_mma<<<dim3(TT / 64, BB * NH), 128, 73728>>>(q16, k16, v16, a16);

    gemm_out<<<dim3(DD / 128, MM / 64), 128, 73728>>>(a16, wo16, out,
                                                      MM, DD, DD);
}